// round 3
// baseline (speedup 1.0000x reference)
#include <cuda_runtime.h>

// Problem constants (fixed by the dataset: pcd [8, 4096, 3] fp32, k = 5)
#define NB 8
#define NPTS 4096
#define KNN 5
#define NHALF 2048
#define TPB 64
#define CHUNKS (NPTS / TPB)        // 64 query chunks per batch
#define BUFCAP 24
#define FLUSH_AT 16

// Scratch (allocation-free rule -> __device__ globals)
__device__ float g_key[2][NB * NPTS * KNN];
__device__ int   g_idx[2][NB * NPTS * KNN];
__device__ float g_partial[NB * 16];   // per-merge-CTA trace partial sums

// --------------------------------------------------------------------------
// Kernel A: per-(query, point-half) top-5 scan with deferred insertion.
// CTA = 64 queries x one half (2048 points, 32KB smem as float4(x,y,z,|p|^2)).
// Hot loop: 1 LDS.128 + 3 FFMA + 1 FSETP + rare buffered append.
// key_j = |p_j|^2 - 2 q.p_j (monotone in d^2; strict '<' in the exact insert
// keeps the lowest index on ties, matching jax.lax.top_k).
// --------------------------------------------------------------------------
__global__ __launch_bounds__(TPB) void knn_scan_kernel(const float* __restrict__ pcd)
{
    __shared__ float4 sh[NHALF];

    const int half  = blockIdx.x & 1;
    const int chunk = (blockIdx.x >> 1) % CHUNKS;
    const int b     = blockIdx.x / (2 * CHUNKS);

    const float* base = pcd + (size_t)b * NPTS * 3;
    const int p0 = half * NHALF;

    for (int p = threadIdx.x; p < NHALF; p += TPB) {
        float x = base[(p0 + p) * 3 + 0];
        float y = base[(p0 + p) * 3 + 1];
        float z = base[(p0 + p) * 3 + 2];
        sh[p] = make_float4(x, y, z, fmaf(x, x, fmaf(y, y, z * z)));
    }
    __syncthreads();

    const int qi = chunk * TPB + threadIdx.x;
    const float qx = base[qi * 3 + 0];
    const float qy = base[qi * 3 + 1];
    const float qz = base[qi * 3 + 2];
    const float nx = -2.0f * qx, ny = -2.0f * qy, nz = -2.0f * qz;

    // Exact sorted top-5 (ascending); scalars -> registers.
    float bk0 = 3.4e38f, bk1 = 3.4e38f, bk2 = 3.4e38f, bk3 = 3.4e38f, bk4 = 3.4e38f;
    int   bi0 = 0, bi1 = 0, bi2 = 0, bi3 = 0, bi4 = 0;

#define INSERT(KEY, JIDX)                                                     \
    {                                                                         \
        float key = (KEY);                                                    \
        if (key < bk4) {                                                      \
            bool lt0 = key < bk0;                                             \
            bool lt1 = key < bk1;                                             \
            bool lt2 = key < bk2;                                             \
            bool lt3 = key < bk3;                                             \
            bk4 = lt3 ? bk3 : key;  bi4 = lt3 ? bi3 : (JIDX);                 \
            if (lt3) { bk3 = lt2 ? bk2 : key;  bi3 = lt2 ? bi2 : (JIDX); }    \
            if (lt2) { bk2 = lt1 ? bk1 : key;  bi2 = lt1 ? bi1 : (JIDX); }    \
            if (lt1) { bk1 = lt0 ? bk0 : key;  bi1 = lt0 ? bi0 : (JIDX); }    \
            if (lt0) { bk0 = key;              bi0 = (JIDX); }                \
        }                                                                     \
    }

    float2 buf[BUFCAP];          // local-memory candidate buffer
    int cnt = 0;
    float thr = 3.4e38f;         // stale >= true 5th key: never drops a candidate

    for (int j = 0; j < NHALF; j += 8) {
#pragma unroll
        for (int u = 0; u < 8; u++) {
            float4 p = sh[j + u];
            float key = fmaf(p.x, nx, fmaf(p.y, ny, fmaf(p.z, nz, p.w)));
            if (key < thr) {
                buf[cnt] = make_float2(key, __int_as_float(p0 + j + u));
                cnt++;
            }
        }
        if (__any_sync(0xffffffffu, cnt >= FLUSH_AT)) {
            for (int i = 0; i < cnt; i++) {
                float2 e = buf[i];
                INSERT(e.x, __float_as_int(e.y));
            }
            cnt = 0;
            thr = bk4;
        }
    }
    for (int i = 0; i < cnt; i++) {
        float2 e = buf[i];
        INSERT(e.x, __float_as_int(e.y));
    }
#undef INSERT

    const size_t o = ((size_t)b * NPTS + qi) * KNN;
    g_key[half][o + 0] = bk0;  g_idx[half][o + 0] = bi0;
    g_key[half][o + 1] = bk1;  g_idx[half][o + 1] = bi1;
    g_key[half][o + 2] = bk2;  g_idx[half][o + 2] = bi2;
    g_key[half][o + 3] = bk3;  g_idx[half][o + 3] = bi3;
    g_key[half][o + 4] = bk4;  g_idx[half][o + 4] = bi4;
}

// --------------------------------------------------------------------------
// Kernel B: merge the two sorted 5-lists per query (rank counting; half0 /
// lower index wins ties), gather neighbors, compute covariance trace.
// Also emits a deterministic per-CTA partial sum of traces for finalize.
// CTA = 256 consecutive queries of one batch (16 CTAs per batch).
// --------------------------------------------------------------------------
__global__ __launch_bounds__(256) void merge_trace_kernel(
    const float* __restrict__ pcd, float* __restrict__ out)
{
    __shared__ float warp_sums[8];

    const int t = blockIdx.x * 256 + threadIdx.x;   // 0 .. NB*NPTS-1
    const int b = t >> 12;

    float ak[KNN], ck[KNN];
    int   ai[KNN], ci[KNN];
    const size_t o = (size_t)t * KNN;
#pragma unroll
    for (int i = 0; i < KNN; i++) {
        ak[i] = g_key[0][o + i];  ai[i] = g_idx[0][o + i];
        ck[i] = g_key[1][o + i];  ci[i] = g_idx[1][o + i];
    }

    float w[2 * KNN];
#pragma unroll
    for (int i = 0; i < KNN; i++) {
        int r = i;
#pragma unroll
        for (int j = 0; j < KNN; j++) r += (ck[j] < ak[i]);
        w[i] = (r < KNN) ? 1.0f : 0.0f;
    }
#pragma unroll
    for (int j = 0; j < KNN; j++) {
        int r = j;
#pragma unroll
        for (int i = 0; i < KNN; i++) r += (ak[i] <= ck[j]);
        w[KNN + j] = (r < KNN) ? 1.0f : 0.0f;
    }

    const float* base = pcd + (size_t)b * NPTS * 3;
    float px[2 * KNN], py[2 * KNN], pz[2 * KNN];
#pragma unroll
    for (int c = 0; c < 2 * KNN; c++) {
        int idx = (c < KNN) ? ai[c] : ci[c - KNN];
        px[c] = base[idx * 3 + 0];
        py[c] = base[idx * 3 + 1];
        pz[c] = base[idx * 3 + 2];
    }

    float sx = 0.f, sy = 0.f, sz = 0.f;
#pragma unroll
    for (int c = 0; c < 2 * KNN; c++) {
        sx = fmaf(w[c], px[c], sx);
        sy = fmaf(w[c], py[c], sy);
        sz = fmaf(w[c], pz[c], sz);
    }
    const float inv_k = 1.0f / (float)KNN;
    const float mx = sx * inv_k, my = sy * inv_k, mz = sz * inv_k;

    float tr = 0.f;
#pragma unroll
    for (int c = 0; c < 2 * KNN; c++) {
        float dx = px[c] - mx, dy = py[c] - my, dz = pz[c] - mz;
        tr = fmaf(w[c], fmaf(dx, dx, fmaf(dy, dy, dz * dz)), tr);
    }
    tr *= 1.0f / (float)(KNN - 1);
    out[t] = tr;

    // Deterministic block reduction of traces (fixed shuffle/smem tree).
    float s = tr;
#pragma unroll
    for (int off = 16; off > 0; off >>= 1)
        s += __shfl_down_sync(0xffffffffu, s, off);
    if ((threadIdx.x & 31) == 0) warp_sums[threadIdx.x >> 5] = s;
    __syncthreads();
    if (threadIdx.x < 32) {
        float v = (threadIdx.x < 8) ? warp_sums[threadIdx.x] : 0.0f;
#pragma unroll
        for (int off = 4; off > 0; off >>= 1)
            v += __shfl_down_sync(0xffffffffu, v, off);
        if (threadIdx.x == 0) g_partial[blockIdx.x] = v;
    }
}

// --------------------------------------------------------------------------
// Kernel C: normalize. 4 CTAs per batch; each sums its batch's 16 partials
// with a fixed-order tree (deterministic, identical across the 4 CTAs) and
// scales its quarter of the batch.
// --------------------------------------------------------------------------
__global__ __launch_bounds__(256) void finalize_kernel(float* __restrict__ out)
{
    __shared__ float s_inv;
    const int b = blockIdx.x >> 2;
    const int quarter = blockIdx.x & 3;

    if (threadIdx.x < 32) {
        float v = (threadIdx.x < 16) ? g_partial[b * 16 + threadIdx.x] : 0.0f;
#pragma unroll
        for (int off = 8; off > 0; off >>= 1)
            v += __shfl_down_sync(0xffffffffu, v, off);
        if (threadIdx.x == 0) s_inv = 1.0f / (v + 1e-8f);
    }
    __syncthreads();

    const float inv = s_inv;
    float* o = out + (size_t)b * NPTS + quarter * (NPTS / 4);
#pragma unroll
    for (int i = 0; i < (NPTS / 4) / 256; i++)
        o[i * 256 + threadIdx.x] *= inv;
}

extern "C" void kernel_launch(void* const* d_in, const int* in_sizes, int n_in,
                              void* d_out, int out_size)
{
    const float* pcd = (const float*)d_in[0];
    float* out = (float*)d_out;

    knn_scan_kernel<<<NB * CHUNKS * 2, TPB>>>(pcd);          // 1024 CTAs
    merge_trace_kernel<<<(NB * NPTS) / 256, 256>>>(pcd, out); // 128 CTAs
    finalize_kernel<<<NB * 4, 256>>>(out);                    // 32 CTAs
}

// round 4
// speedup vs baseline: 1.3408x; 1.3408x over previous
#include <cuda_runtime.h>

// Problem constants (fixed by the dataset: pcd [8, 4096, 3] fp32, k = 5)
#define NB 8
#define NPTS 4096
#define KNN 5
#define NHALF 2048
#define TPB 128
#define CHUNKS (NPTS / TPB)        // 32 query chunks per batch

// Scratch (allocation-free rule -> __device__ globals)
__device__ float g_key[2][NB * NPTS * KNN];
__device__ int   g_idx[2][NB * NPTS * KNN];
__device__ float g_partial[NB * 16];   // per-merge-CTA trace partial sums

// --------------------------------------------------------------------------
// Kernel A: per-(query, point-half) top-5 scan.
// CTA = 128 queries x one half of the points (2048, staged in 32KB smem as
// float4(x,y,z,|p|^2)). Inner loop: group-of-8 batched LDS.128, all 8 keys
// computed straight-line, then 8 individually-guarded register inserts.
// key_j = |p_j|^2 - 2 q.p_j (monotone in d^2 for fixed q; strict '<'
// displacement keeps the lowest index on ties, matching jax.lax.top_k).
// --------------------------------------------------------------------------
__global__ __launch_bounds__(TPB) void knn_scan_kernel(const float* __restrict__ pcd)
{
    __shared__ float4 sh[NHALF];

    const int half  = blockIdx.x & 1;
    const int chunk = (blockIdx.x >> 1) % CHUNKS;
    const int b     = blockIdx.x / (2 * CHUNKS);

    const float* base = pcd + (size_t)b * NPTS * 3;
    const int p0 = half * NHALF;

    for (int p = threadIdx.x; p < NHALF; p += TPB) {
        float x = base[(p0 + p) * 3 + 0];
        float y = base[(p0 + p) * 3 + 1];
        float z = base[(p0 + p) * 3 + 2];
        sh[p] = make_float4(x, y, z, fmaf(x, x, fmaf(y, y, z * z)));
    }
    __syncthreads();

    const int qi = chunk * TPB + threadIdx.x;
    const float qx = base[qi * 3 + 0];
    const float qy = base[qi * 3 + 1];
    const float qz = base[qi * 3 + 2];
    const float nx = -2.0f * qx, ny = -2.0f * qy, nz = -2.0f * qz;

    // Exact sorted top-5 (ascending); named scalars -> registers.
    float bk0 = 3.4e38f, bk1 = 3.4e38f, bk2 = 3.4e38f, bk3 = 3.4e38f, bk4 = 3.4e38f;
    int   bi0 = 0, bi1 = 0, bi2 = 0, bi3 = 0, bi4 = 0;

#define INSERT(KEY, JIDX)                                                     \
    {                                                                         \
        float key = (KEY);                                                    \
        if (key < bk4) {                                                      \
            bool lt0 = key < bk0;                                             \
            bool lt1 = key < bk1;                                             \
            bool lt2 = key < bk2;                                             \
            bool lt3 = key < bk3;                                             \
            bk4 = lt3 ? bk3 : key;  bi4 = lt3 ? bi3 : (JIDX);                 \
            if (lt3) { bk3 = lt2 ? bk2 : key;  bi3 = lt2 ? bi2 : (JIDX); }    \
            if (lt2) { bk2 = lt1 ? bk1 : key;  bi2 = lt1 ? bi1 : (JIDX); }    \
            if (lt1) { bk1 = lt0 ? bk0 : key;  bi1 = lt0 ? bi0 : (JIDX); }    \
            if (lt0) { bk0 = key;              bi0 = (JIDX); }                \
        }                                                                     \
    }

    for (int j = 0; j < NHALF; j += 8) {
        // Batched loads: 8 x LDS.128 issue back-to-back (one basic block).
        float4 p0v = sh[j + 0];
        float4 p1v = sh[j + 1];
        float4 p2v = sh[j + 2];
        float4 p3v = sh[j + 3];
        float4 p4v = sh[j + 4];
        float4 p5v = sh[j + 5];
        float4 p6v = sh[j + 6];
        float4 p7v = sh[j + 7];
        // All keys straight-line before any branch.
        float k0 = fmaf(p0v.x, nx, fmaf(p0v.y, ny, fmaf(p0v.z, nz, p0v.w)));
        float k1 = fmaf(p1v.x, nx, fmaf(p1v.y, ny, fmaf(p1v.z, nz, p1v.w)));
        float k2 = fmaf(p2v.x, nx, fmaf(p2v.y, ny, fmaf(p2v.z, nz, p2v.w)));
        float k3 = fmaf(p3v.x, nx, fmaf(p3v.y, ny, fmaf(p3v.z, nz, p3v.w)));
        float k4 = fmaf(p4v.x, nx, fmaf(p4v.y, ny, fmaf(p4v.z, nz, p4v.w)));
        float k5 = fmaf(p5v.x, nx, fmaf(p5v.y, ny, fmaf(p5v.z, nz, p5v.w)));
        float k6 = fmaf(p6v.x, nx, fmaf(p6v.y, ny, fmaf(p6v.z, nz, p6v.w)));
        float k7 = fmaf(p7v.x, nx, fmaf(p7v.y, ny, fmaf(p7v.z, nz, p7v.w)));
        INSERT(k0, p0 + j + 0);
        INSERT(k1, p0 + j + 1);
        INSERT(k2, p0 + j + 2);
        INSERT(k3, p0 + j + 3);
        INSERT(k4, p0 + j + 4);
        INSERT(k5, p0 + j + 5);
        INSERT(k6, p0 + j + 6);
        INSERT(k7, p0 + j + 7);
    }
#undef INSERT

    const size_t o = ((size_t)b * NPTS + qi) * KNN;
    g_key[half][o + 0] = bk0;  g_idx[half][o + 0] = bi0;
    g_key[half][o + 1] = bk1;  g_idx[half][o + 1] = bi1;
    g_key[half][o + 2] = bk2;  g_idx[half][o + 2] = bi2;
    g_key[half][o + 3] = bk3;  g_idx[half][o + 3] = bi3;
    g_key[half][o + 4] = bk4;  g_idx[half][o + 4] = bi4;
}

// --------------------------------------------------------------------------
// Kernel B: merge the two sorted 5-lists per query (rank counting; half0 /
// lower index wins ties), gather neighbors, compute covariance trace.
// Also emits a deterministic per-CTA partial sum of traces for finalize.
// --------------------------------------------------------------------------
__global__ __launch_bounds__(256) void merge_trace_kernel(
    const float* __restrict__ pcd, float* __restrict__ out)
{
    __shared__ float warp_sums[8];

    const int t = blockIdx.x * 256 + threadIdx.x;   // 0 .. NB*NPTS-1
    const int b = t >> 12;

    float ak[KNN], ck[KNN];
    int   ai[KNN], ci[KNN];
    const size_t o = (size_t)t * KNN;
#pragma unroll
    for (int i = 0; i < KNN; i++) {
        ak[i] = g_key[0][o + i];  ai[i] = g_idx[0][o + i];
        ck[i] = g_key[1][o + i];  ci[i] = g_idx[1][o + i];
    }

    float w[2 * KNN];
#pragma unroll
    for (int i = 0; i < KNN; i++) {
        int r = i;
#pragma unroll
        for (int j = 0; j < KNN; j++) r += (ck[j] < ak[i]);   // half1 first only if strictly smaller
        w[i] = (r < KNN) ? 1.0f : 0.0f;
    }
#pragma unroll
    for (int j = 0; j < KNN; j++) {
        int r = j;
#pragma unroll
        for (int i = 0; i < KNN; i++) r += (ak[i] <= ck[j]);  // half0 first on ties
        w[KNN + j] = (r < KNN) ? 1.0f : 0.0f;
    }

    const float* base = pcd + (size_t)b * NPTS * 3;
    float px[2 * KNN], py[2 * KNN], pz[2 * KNN];
#pragma unroll
    for (int c = 0; c < 2 * KNN; c++) {
        int idx = (c < KNN) ? ai[c] : ci[c - KNN];
        px[c] = base[idx * 3 + 0];
        py[c] = base[idx * 3 + 1];
        pz[c] = base[idx * 3 + 2];
    }

    float sx = 0.f, sy = 0.f, sz = 0.f;
#pragma unroll
    for (int c = 0; c < 2 * KNN; c++) {
        sx = fmaf(w[c], px[c], sx);
        sy = fmaf(w[c], py[c], sy);
        sz = fmaf(w[c], pz[c], sz);
    }
    const float inv_k = 1.0f / (float)KNN;
    const float mx = sx * inv_k, my = sy * inv_k, mz = sz * inv_k;

    float tr = 0.f;
#pragma unroll
    for (int c = 0; c < 2 * KNN; c++) {
        float dx = px[c] - mx, dy = py[c] - my, dz = pz[c] - mz;
        tr = fmaf(w[c], fmaf(dx, dx, fmaf(dy, dy, dz * dz)), tr);
    }
    tr *= 1.0f / (float)(KNN - 1);
    out[t] = tr;

    // Deterministic block reduction (fixed shuffle/smem tree).
    float s = tr;
#pragma unroll
    for (int off = 16; off > 0; off >>= 1)
        s += __shfl_down_sync(0xffffffffu, s, off);
    if ((threadIdx.x & 31) == 0) warp_sums[threadIdx.x >> 5] = s;
    __syncthreads();
    if (threadIdx.x < 32) {
        float v = (threadIdx.x < 8) ? warp_sums[threadIdx.x] : 0.0f;
#pragma unroll
        for (int off = 4; off > 0; off >>= 1)
            v += __shfl_down_sync(0xffffffffu, v, off);
        if (threadIdx.x == 0) g_partial[blockIdx.x] = v;
    }
}

// --------------------------------------------------------------------------
// Kernel C: normalize. 4 CTAs per batch; each redundantly sums its batch's
// 16 partials with a fixed-order tree (deterministic) and scales its quarter.
// --------------------------------------------------------------------------
__global__ __launch_bounds__(256) void finalize_kernel(float* __restrict__ out)
{
    __shared__ float s_inv;
    const int b = blockIdx.x >> 2;
    const int quarter = blockIdx.x & 3;

    if (threadIdx.x < 32) {
        float v = (threadIdx.x < 16) ? g_partial[b * 16 + threadIdx.x] : 0.0f;
#pragma unroll
        for (int off = 8; off > 0; off >>= 1)
            v += __shfl_down_sync(0xffffffffu, v, off);
        if (threadIdx.x == 0) s_inv = 1.0f / (v + 1e-8f);
    }
    __syncthreads();

    const float inv = s_inv;
    float* o = out + (size_t)b * NPTS + quarter * (NPTS / 4);
#pragma unroll
    for (int i = 0; i < (NPTS / 4) / 256; i++)
        o[i * 256 + threadIdx.x] *= inv;
}

extern "C" void kernel_launch(void* const* d_in, const int* in_sizes, int n_in,
                              void* d_out, int out_size)
{
    const float* pcd = (const float*)d_in[0];
    float* out = (float*)d_out;

    knn_scan_kernel<<<NB * CHUNKS * 2, TPB>>>(pcd);           // 512 CTAs
    merge_trace_kernel<<<(NB * NPTS) / 256, 256>>>(pcd, out); // 128 CTAs
    finalize_kernel<<<NB * 4, 256>>>(out);                    // 32 CTAs
}

// round 6
// speedup vs baseline: 1.3993x; 1.0436x over previous
#include <cuda_runtime.h>

// Problem constants (fixed by the dataset: pcd [8, 4096, 3] fp32, k = 5)
#define NB 8
#define NPTS 4096
#define KNN 5
#define NSPLIT 4
#define MSEG (NPTS / NSPLIT)       // 1024 points per segment
#define TPB 128
#define CHUNKS (NPTS / TPB)        // 32 query chunks per batch

// Scratch (allocation-free rule -> __device__ globals)
__device__ float g_key[NSPLIT][NB * NPTS * KNN];
__device__ int   g_idx[NSPLIT][NB * NPTS * KNN];
__device__ float g_partial[NB * 16];   // per-merge-CTA trace partial sums

// --------------------------------------------------------------------------
// Kernel A: per-(query, point-segment) top-5 scan.
// CTA = 128 queries x one quarter of the points (1024, staged in 16KB smem
// as float4(x,y,z,|p|^2)). Inner loop: group-of-8 batched LDS.128, all 8
// keys straight-line, then 8 individually-guarded register inserts.
// key_j = |p_j|^2 - 2 q.p_j (monotone in d^2 for fixed q; strict '<'
// displacement keeps the lowest index on ties, matching jax.lax.top_k).
// --------------------------------------------------------------------------
__global__ __launch_bounds__(TPB) void knn_scan_kernel(const float* __restrict__ pcd)
{
    __shared__ float4 sh[MSEG];

    const int seg   = blockIdx.x & (NSPLIT - 1);
    const int chunk = (blockIdx.x >> 2) % CHUNKS;
    const int b     = blockIdx.x / (NSPLIT * CHUNKS);

    const float* base = pcd + (size_t)b * NPTS * 3;
    const int p0 = seg * MSEG;

    for (int p = threadIdx.x; p < MSEG; p += TPB) {
        float x = base[(p0 + p) * 3 + 0];
        float y = base[(p0 + p) * 3 + 1];
        float z = base[(p0 + p) * 3 + 2];
        sh[p] = make_float4(x, y, z, fmaf(x, x, fmaf(y, y, z * z)));
    }
    __syncthreads();

    const int qi = chunk * TPB + threadIdx.x;
    const float qx = base[qi * 3 + 0];
    const float qy = base[qi * 3 + 1];
    const float qz = base[qi * 3 + 2];
    const float nx = -2.0f * qx, ny = -2.0f * qy, nz = -2.0f * qz;

    // Exact sorted top-5 (ascending); named scalars -> registers.
    float bk0 = 3.4e38f, bk1 = 3.4e38f, bk2 = 3.4e38f, bk3 = 3.4e38f, bk4 = 3.4e38f;
    int   bi0 = 0, bi1 = 0, bi2 = 0, bi3 = 0, bi4 = 0;

#define INSERT(KEY, JIDX)                                                     \
    {                                                                         \
        float key = (KEY);                                                    \
        if (key < bk4) {                                                      \
            bool lt0 = key < bk0;                                             \
            bool lt1 = key < bk1;                                             \
            bool lt2 = key < bk2;                                             \
            bool lt3 = key < bk3;                                             \
            bk4 = lt3 ? bk3 : key;  bi4 = lt3 ? bi3 : (JIDX);                 \
            if (lt3) { bk3 = lt2 ? bk2 : key;  bi3 = lt2 ? bi2 : (JIDX); }    \
            if (lt2) { bk2 = lt1 ? bk1 : key;  bi2 = lt1 ? bi1 : (JIDX); }    \
            if (lt1) { bk1 = lt0 ? bk0 : key;  bi1 = lt0 ? bi0 : (JIDX); }    \
            if (lt0) { bk0 = key;              bi0 = (JIDX); }                \
        }                                                                     \
    }

    for (int j = 0; j < MSEG; j += 8) {
        // Batched loads: 8 x LDS.128 issue back-to-back (one basic block).
        float4 p0v = sh[j + 0];
        float4 p1v = sh[j + 1];
        float4 p2v = sh[j + 2];
        float4 p3v = sh[j + 3];
        float4 p4v = sh[j + 4];
        float4 p5v = sh[j + 5];
        float4 p6v = sh[j + 6];
        float4 p7v = sh[j + 7];
        // All keys straight-line before any branch.
        float k0 = fmaf(p0v.x, nx, fmaf(p0v.y, ny, fmaf(p0v.z, nz, p0v.w)));
        float k1 = fmaf(p1v.x, nx, fmaf(p1v.y, ny, fmaf(p1v.z, nz, p1v.w)));
        float k2 = fmaf(p2v.x, nx, fmaf(p2v.y, ny, fmaf(p2v.z, nz, p2v.w)));
        float k3 = fmaf(p3v.x, nx, fmaf(p3v.y, ny, fmaf(p3v.z, nz, p3v.w)));
        float k4 = fmaf(p4v.x, nx, fmaf(p4v.y, ny, fmaf(p4v.z, nz, p4v.w)));
        float k5 = fmaf(p5v.x, nx, fmaf(p5v.y, ny, fmaf(p5v.z, nz, p5v.w)));
        float k6 = fmaf(p6v.x, nx, fmaf(p6v.y, ny, fmaf(p6v.z, nz, p6v.w)));
        float k7 = fmaf(p7v.x, nx, fmaf(p7v.y, ny, fmaf(p7v.z, nz, p7v.w)));
        INSERT(k0, p0 + j + 0);
        INSERT(k1, p0 + j + 1);
        INSERT(k2, p0 + j + 2);
        INSERT(k3, p0 + j + 3);
        INSERT(k4, p0 + j + 4);
        INSERT(k5, p0 + j + 5);
        INSERT(k6, p0 + j + 6);
        INSERT(k7, p0 + j + 7);
    }
#undef INSERT

    const size_t o = ((size_t)b * NPTS + qi) * KNN;
    g_key[seg][o + 0] = bk0;  g_idx[seg][o + 0] = bi0;
    g_key[seg][o + 1] = bk1;  g_idx[seg][o + 1] = bi1;
    g_key[seg][o + 2] = bk2;  g_idx[seg][o + 2] = bi2;
    g_key[seg][o + 3] = bk3;  g_idx[seg][o + 3] = bi3;
    g_key[seg][o + 4] = bk4;  g_idx[seg][o + 4] = bi4;
}

// --------------------------------------------------------------------------
// Kernel B: merge the four sorted 5-lists per query by rank counting.
// Global order = (key, segment, in-list position): segment t precedes a
// later segment s on ties (lower indices), expressed as '<=' vs '<'.
// Then gather neighbors and compute the covariance trace with the
// reference's centroid-then-centered numerics. Emits per-CTA partial sums.
// --------------------------------------------------------------------------
__global__ __launch_bounds__(256) void merge_trace_kernel(
    const float* __restrict__ pcd, float* __restrict__ out)
{
    __shared__ float warp_sums[8];

    const int t = blockIdx.x * 256 + threadIdx.x;   // 0 .. NB*NPTS-1
    const int b = t >> 12;

    float k[NSPLIT][KNN];
    int   ix[NSPLIT][KNN];
    const size_t o = (size_t)t * KNN;
#pragma unroll
    for (int s = 0; s < NSPLIT; s++)
#pragma unroll
        for (int i = 0; i < KNN; i++) {
            k[s][i]  = g_key[s][o + i];
            ix[s][i] = g_idx[s][o + i];
        }

    // Selection weights by global rank among the 20 candidates.
    float w[NSPLIT][KNN];
#pragma unroll
    for (int s = 0; s < NSPLIT; s++) {
#pragma unroll
        for (int i = 0; i < KNN; i++) {
            int r = i;  // predecessors within own (sorted) list
#pragma unroll
            for (int u = 0; u < NSPLIT; u++) {
                if (u == s) continue;
#pragma unroll
                for (int j = 0; j < KNN; j++) {
                    if (u < s) r += (k[u][j] <= k[s][i]);  // earlier segment wins ties
                    else       r += (k[u][j] <  k[s][i]);
                }
            }
            w[s][i] = (r < KNN) ? 1.0f : 0.0f;
        }
    }

    // Gather the 20 candidate coordinates (5 carry weight 1).
    const float* base = pcd + (size_t)b * NPTS * 3;
    float px[NSPLIT][KNN], py[NSPLIT][KNN], pz[NSPLIT][KNN];
#pragma unroll
    for (int s = 0; s < NSPLIT; s++)
#pragma unroll
        for (int i = 0; i < KNN; i++) {
            int idx = ix[s][i];
            px[s][i] = base[idx * 3 + 0];
            py[s][i] = base[idx * 3 + 1];
            pz[s][i] = base[idx * 3 + 2];
        }

    float sx = 0.f, sy = 0.f, sz = 0.f;
#pragma unroll
    for (int s = 0; s < NSPLIT; s++)
#pragma unroll
        for (int i = 0; i < KNN; i++) {
            sx = fmaf(w[s][i], px[s][i], sx);
            sy = fmaf(w[s][i], py[s][i], sy);
            sz = fmaf(w[s][i], pz[s][i], sz);
        }
    const float inv_k = 1.0f / (float)KNN;
    const float mx = sx * inv_k, my = sy * inv_k, mz = sz * inv_k;

    float tr = 0.f;
#pragma unroll
    for (int s = 0; s < NSPLIT; s++)
#pragma unroll
        for (int i = 0; i < KNN; i++) {
            float dx = px[s][i] - mx, dy = py[s][i] - my, dz = pz[s][i] - mz;
            tr = fmaf(w[s][i], fmaf(dx, dx, fmaf(dy, dy, dz * dz)), tr);
        }
    tr *= 1.0f / (float)(KNN - 1);
    out[t] = tr;

    // Deterministic block reduction (fixed shuffle/smem tree).
    float s0 = tr;
#pragma unroll
    for (int off = 16; off > 0; off >>= 1)
        s0 += __shfl_down_sync(0xffffffffu, s0, off);
    if ((threadIdx.x & 31) == 0) warp_sums[threadIdx.x >> 5] = s0;
    __syncthreads();
    if (threadIdx.x < 32) {
        float v = (threadIdx.x < 8) ? warp_sums[threadIdx.x] : 0.0f;
#pragma unroll
        for (int off = 4; off > 0; off >>= 1)
            v += __shfl_down_sync(0xffffffffu, v, off);
        if (threadIdx.x == 0) g_partial[blockIdx.x] = v;
    }
}

// --------------------------------------------------------------------------
// Kernel C: normalize. 4 CTAs per batch; each redundantly sums its batch's
// 16 partials with a fixed-order tree (deterministic) and scales its quarter.
// --------------------------------------------------------------------------
__global__ __launch_bounds__(256) void finalize_kernel(float* __restrict__ out)
{
    __shared__ float s_inv;
    const int b = blockIdx.x >> 2;
    const int quarter = blockIdx.x & 3;

    if (threadIdx.x < 32) {
        float v = (threadIdx.x < 16) ? g_partial[b * 16 + threadIdx.x] : 0.0f;
#pragma unroll
        for (int off = 8; off > 0; off >>= 1)
            v += __shfl_down_sync(0xffffffffu, v, off);
        if (threadIdx.x == 0) s_inv = 1.0f / (v + 1e-8f);
    }
    __syncthreads();

    const float inv = s_inv;
    float* o = out + (size_t)b * NPTS + quarter * (NPTS / 4);
#pragma unroll
    for (int i = 0; i < (NPTS / 4) / 256; i++)
        o[i * 256 + threadIdx.x] *= inv;
}

extern "C" void kernel_launch(void* const* d_in, const int* in_sizes, int n_in,
                              void* d_out, int out_size)
{
    const float* pcd = (const float*)d_in[0];
    float* out = (float*)d_out;

    knn_scan_kernel<<<NB * CHUNKS * NSPLIT, TPB>>>(pcd);      // 1024 CTAs
    merge_trace_kernel<<<(NB * NPTS) / 256, 256>>>(pcd, out); // 128 CTAs
    finalize_kernel<<<NB * 4, 256>>>(out);                    // 32 CTAs
}